// round 9
// baseline (speedup 1.0000x reference)
#include <cuda_runtime.h>
#include <cuda_bf16.h>

#define NROWS 32768
#define DIM   256
#define NE    256
#define NQ    4
#define KP    4096

#define OFF_MEAN  (NROWS*DIM)            // 8388608
#define OFF_OUTER (NROWS*DIM + 1)
#define OFF_IDX   (NROWS*DIM + 1 + NQ)   // 8388613

typedef unsigned long long ull;
typedef unsigned int uint;
typedef unsigned short ushort;

// ---------------- device scratch (no allocs allowed) ----------------
__device__ float  g_RES[NROWS*DIM];     // current residual
__device__ float  g_XN [NROWS*DIM];     // normalized residual (fp32)
__device__ float  g_RR [NROWS];         // ||residual||^2 per row
__device__ float2 g_CTP[NQ*128*NE];     // codebook, d-paired + transposed
__device__ float  g_CE [NQ*NE];         // ||e||^2
__device__ float  g_SEXP[KP];           // sum of exp(sim) per pair
__device__ float  g_POS [KP];           // pos logits
__device__ float  g_VQ  [NQ];           // sum of squared new residual
// fp8 (e4m3) copies of 8*xn, row-major, 256B/row
__device__ uint4  g_XNB4[NROWS*DIM/16]; // keys  [32768][256] e4m3
__device__ uint4  g_QB4 [KP*DIM/16];    // queries [4096][256] e4m3

// ---------------- helpers ----------------
__device__ __forceinline__ ull bc2(float a) {
    ull r; asm("mov.b64 %0, {%1, %1};" : "=l"(r) : "f"(a)); return r;
}
__device__ __forceinline__ float2 u2f(ull u) {
    float2 f;
    f.x = __uint_as_float((unsigned)(u & 0xffffffffu));
    f.y = __uint_as_float((unsigned)(u >> 32));
    return f;
}
__device__ __forceinline__ void fma2(ull &acc, ull a, ull b) {
    asm("fma.rn.f32x2 %0, %1, %2, %0;" : "+l"(acc) : "l"(a), "l"(b));
}
__device__ __forceinline__ uint smem_u32(const void* p) {
    return (uint)__cvta_generic_to_shared(p);
}
// pack 4 fp32 -> 4 e4m3 bytes (byte0 = f0 .. byte3 = f3)
__device__ __forceinline__ uint pack_e4m3x4(float f0, float f1, float f2, float f3) {
    ushort lo, hi;
    asm("cvt.rn.satfinite.e4m3x2.f32 %0, %1, %2;" : "=h"(lo) : "f"(f1), "f"(f0));
    asm("cvt.rn.satfinite.e4m3x2.f32 %0, %1, %2;" : "=h"(hi) : "f"(f3), "f"(f2));
    return (uint)lo | ((uint)hi << 16);
}
__device__ __forceinline__ void cp16(uint dst, const void* src) {
    asm volatile("cp.async.cg.shared.global [%0], [%1], 16;"
                 :: "r"(dst), "l"(src) : "memory");
}
__device__ __forceinline__ void ldm4(uint &r0, uint &r1, uint &r2, uint &r3, uint addr) {
    asm volatile("ldmatrix.sync.aligned.m8n8.x4.shared.b16 {%0,%1,%2,%3}, [%4];"
                 : "=r"(r0), "=r"(r1), "=r"(r2), "=r"(r3) : "r"(addr));
}
// fp8 e4m3 MMA, m16n8k32, fp32 accumulate
__device__ __forceinline__ void mma_fp8(float* c, const uint* a, const uint* b) {
    asm volatile(
        "mma.sync.aligned.m16n8k32.row.col.f32.e4m3.e4m3.f32 "
        "{%0,%1,%2,%3}, {%4,%5,%6,%7}, {%8,%9}, {%0,%1,%2,%3};"
        : "+f"(c[0]), "+f"(c[1]), "+f"(c[2]), "+f"(c[3])
        : "r"(a[0]), "r"(a[1]), "r"(a[2]), "r"(a[3]), "r"(b[0]), "r"(b[1]));
}

// block reduce (256 threads), result valid on thread 0
__device__ __forceinline__ float blockReduceSum256(float v, float* sbuf) {
    #pragma unroll
    for (int o = 16; o; o >>= 1) v += __shfl_down_sync(0xffffffffu, v, o);
    int w = threadIdx.x >> 5, l = threadIdx.x & 31;
    if (l == 0) sbuf[w] = v;
    __syncthreads();
    if (w == 0) {
        v = (l < 8) ? sbuf[l] : 0.f;
        #pragma unroll
        for (int o = 4; o; o >>= 1) v += __shfl_down_sync(0xffffffffu, v, o);
    }
    return v;
}

// ---------------- kernels ----------------

__global__ void k_init(const float* __restrict__ x) {
    int i = blockIdx.x * 256 + threadIdx.x;
    ((float4*)g_RES)[i] = ((const float4*)x)[i];
    if (i < NQ) g_VQ[i] = 0.f;
}

__global__ void k_prep(const float* __restrict__ CB) {
    __shared__ float sbuf[8];
    int q = blockIdx.y, j = blockIdx.x, d = threadIdx.x;
    const float* row = CB + ((size_t)q * NE + j) * DIM;
    float v = row[d];
    float s = blockReduceSum256(v * v, sbuf);
    if (d == 0) g_CE[q * NE + j] = s;
    if (d < 128) {
        float2 p; p.x = row[2*d]; p.y = row[2*d + 1];
        g_CTP[(q * 128 + d) * NE + j] = p;
    }
}

// normalize row; write fp32 XN and e4m3 copy of 8*xn
__global__ void k_norm() {
    __shared__ float sbuf[8];
    __shared__ float stot;
    __shared__ float rowv[DIM];
    int row = blockIdx.x, d = threadIdx.x;
    float v = g_RES[(size_t)row * DIM + d];
    float s = blockReduceSum256(v * v, sbuf);
    if (d == 0) { stot = s; g_RR[row] = s; }
    __syncthreads();
    float inv = rsqrtf(stot + 1e-12f);
    float xv = v * inv;
    g_XN[(size_t)row * DIM + d] = xv;
    rowv[d] = xv;
    __syncthreads();
    if (d < 64)
        ((uint*)g_XNB4)[(size_t)row * 64 + d] =
            pack_e4m3x4(8.f*rowv[4*d], 8.f*rowv[4*d+1], 8.f*rowv[4*d+2], 8.f*rowv[4*d+3]);
}

// gather queries -> e4m3, compute pos (fp32), zero SEXP
__global__ void k_gather(const int* __restrict__ p1, const int* __restrict__ p2) {
    __shared__ float sbuf[8];
    __shared__ float rowv[DIM];
    int k = blockIdx.x, d = threadIdx.x;
    int i1 = p1[k], i2 = p2[k];
    float a = g_XN[(size_t)i1 * DIM + d];
    float b = g_XN[(size_t)i2 * DIM + d];
    rowv[d] = a;
    float s = blockReduceSum256(a * b, sbuf);
    if (d == 0) { g_POS[k] = s * 10.f; g_SEXP[k] = 0.f; }
    __syncthreads();
    if (d < 64)
        ((uint*)g_QB4)[(size_t)k * 64 + d] =
            pack_e4m3x4(8.f*rowv[4*d], 8.f*rowv[4*d+1], 8.f*rowv[4*d+2], 8.f*rowv[4*d+3]);
}

// ---------------- FP8 MMA LSE GEMM ----------------
// CTA: 128 pairs x 128 keys x K=256 e4m3, fp32 accum. acc = 64*dot.
// 8 warps 2(m) x 4(n); warp tile 64x32 = 4x4 m16n8k32.
// 2 K-chunks of 128 dims (128B/row), double-buffered cp.async, XOR swizzle.
__global__ void __launch_bounds__(256, 2) k_lse_mma() {
    extern __shared__ char dyn[];
    uint sbase = smem_u32(dyn);

    int tid  = threadIdx.x;
    int wid  = tid >> 5, lane = tid & 31;
    int wm   = wid >> 2, wn   = wid & 3;
    int bn   = blockIdx.x, bm = blockIdx.y;

    const char* gA = (const char*)g_QB4  + (size_t)(bm * 128) * 256;
    const char* gB = (const char*)g_XNB4 + (size_t)(bn * 128) * 256;

    float acc[4][4][4];
    #pragma unroll
    for (int mt = 0; mt < 4; mt++)
        #pragma unroll
        for (int nt = 0; nt < 4; nt++)
            #pragma unroll
            for (int i = 0; i < 4; i++) acc[mt][nt][i] = 0.f;

    // chunk: 128 rows x 128 e4m3 (128B/row) for A and B into buffer b
    auto load_chunk = [&](int kc, int b) {
        uint abuf = sbase + (uint)b * 32768u;
        uint bbuf = abuf + 16384u;
        #pragma unroll
        for (int t = 0; t < 4; t++) {
            int i = tid + t * 256;          // 0..1023
            int row = i >> 3, c = i & 7;
            uint soff = (uint)((row * 8 + (c ^ (row & 7))) * 16);
            cp16(abuf + soff, gA + (size_t)row * 256 + kc * 128 + c * 16);
            cp16(bbuf + soff, gB + (size_t)row * 256 + kc * 128 + c * 16);
        }
    };

    load_chunk(0, 0);
    asm volatile("cp.async.commit_group;" ::: "memory");
    load_chunk(1, 1);
    asm volatile("cp.async.commit_group;" ::: "memory");

    #pragma unroll
    for (int kc = 0; kc < 2; kc++) {
        if (kc == 0) asm volatile("cp.async.wait_group 1;" ::: "memory");
        else         asm volatile("cp.async.wait_group 0;" ::: "memory");
        __syncthreads();

        uint abuf = sbase + (uint)kc * 32768u;
        uint bbuf = abuf + 16384u;

        #pragma unroll
        for (int ks = 0; ks < 4; ks++) {     // 32 fp8 dims per step
            uint afr[4][4];
            #pragma unroll
            for (int mt = 0; mt < 4; mt++) {
                int row = wm * 64 + mt * 16 + (lane & 15);
                int chunk = ks * 2 + (lane >> 4);      // 16B unit within 128B row
                uint addr = abuf + (uint)((row * 8 + (chunk ^ (row & 7))) * 16);
                ldm4(afr[mt][0], afr[mt][1], afr[mt][2], afr[mt][3], addr);
            }
            uint bfr[4][2];
            #pragma unroll
            for (int p = 0; p < 2; p++) {
                int g = lane >> 3;
                int ntl = 2 * p + (g >> 1);
                int row = wn * 32 + ntl * 8 + (lane & 7);
                int chunk = ks * 2 + (g & 1);
                uint addr = bbuf + (uint)((row * 8 + (chunk ^ (row & 7))) * 16);
                ldm4(bfr[2*p][0], bfr[2*p][1], bfr[2*p+1][0], bfr[2*p+1][1], addr);
            }
            #pragma unroll
            for (int mt = 0; mt < 4; mt++)
                #pragma unroll
                for (int nt = 0; nt < 4; nt++)
                    mma_fp8(acc[mt][nt], afr[mt], bfr[nt]);
        }
    }

    // epilogue: logits = acc * (10/64); exp + row sums
    float* red = (float*)dyn;   // 128 rows x 4 n-warps
    const float LS = 0.15625f;
    float s0[4], s1[4];
    #pragma unroll
    for (int mt = 0; mt < 4; mt++) {
        float a0 = 0.f, a1 = 0.f;
        #pragma unroll
        for (int nt = 0; nt < 4; nt++) {
            a0 += __expf(LS * acc[mt][nt][0]) + __expf(LS * acc[mt][nt][1]);
            a1 += __expf(LS * acc[mt][nt][2]) + __expf(LS * acc[mt][nt][3]);
        }
        #pragma unroll
        for (int o = 1; o < 4; o <<= 1) {
            a0 += __shfl_xor_sync(0xffffffffu, a0, o);
            a1 += __shfl_xor_sync(0xffffffffu, a1, o);
        }
        s0[mt] = a0; s1[mt] = a1;
    }
    __syncthreads();           // all warps done with smem buffers
    if ((lane & 3) == 0) {
        int rbase = wm * 64 + (lane >> 2);
        #pragma unroll
        for (int mt = 0; mt < 4; mt++) {
            red[(rbase + mt * 16)     * 4 + wn] = s0[mt];
            red[(rbase + mt * 16 + 8) * 4 + wn] = s1[mt];
        }
    }
    __syncthreads();
    if (tid < 128) {
        float s = red[tid * 4] + red[tid * 4 + 1] + red[tid * 4 + 2] + red[tid * 4 + 3];
        atomicAdd(&g_SEXP[bm * 128 + tid], s);
    }
}

__global__ void k_outer(float* __restrict__ out, int q) {
    __shared__ float sbuf[8];
    float acc = 0.f;
    for (int k = threadIdx.x; k < KP; k += 256)
        acc += logf(g_SEXP[k]) - g_POS[k];
    float s = blockReduceSum256(acc, sbuf);
    if (threadIdx.x == 0) out[OFF_OUTER + q] = s / (float)KP;
}

// quantize (reference-rounding-matched distances, fp32; unchanged)
__global__ void __launch_bounds__(256) k_quant(const float* __restrict__ CB,
                                               float* __restrict__ out,
                                               int q, int first) {
    __shared__ float rs[32][DIM];
    __shared__ ull   wmin[32][8];
    __shared__ int   idxs[32];
    __shared__ float sbuf[8];
    __shared__ float rr_s[32];

    int tid = threadIdx.x;
    int i0 = blockIdx.x * 32;

    #pragma unroll
    for (int i = 0; i < 8; i++) {
        int lin = tid + i * 256;
        int m = lin >> 6, c = lin & 63;
        ((float4*)&rs[m][0])[c] = *(const float4*)(g_RES + (size_t)(i0 + m) * DIM + c * 4);
    }
    if (tid < 32) rr_s[tid] = g_RR[i0 + tid];
    __syncthreads();

    int j = tid;
    ull dot2[32];
    #pragma unroll
    for (int m = 0; m < 32; m++) dot2[m] = 0ull;

    const float2* ctp = g_CTP + (size_t)q * 128 * NE;
    #pragma unroll 2
    for (int dpc = 0; dpc < 32; dpc++) {
        ull ct[4];
        #pragma unroll
        for (int c = 0; c < 4; c++)
            ct[c] = *(const ull*)&ctp[(dpc * 4 + c) * NE + j];
        #pragma unroll
        for (int m = 0; m < 32; m++) {
            #pragma unroll
            for (int c = 0; c < 4; c++) {
                ull r2 = *(const ull*)&rs[m][(dpc * 4 + c) * 2];
                fma2(dot2[m], r2, ct[c]);
            }
        }
    }

    float ce = g_CE[q * NE + j];
    #pragma unroll
    for (int m = 0; m < 32; m++) {
        float2 f = u2f(dot2[m]);
        float dotv = f.x + f.y;
        float t1 = fmaf(-2.f, dotv, rr_s[m]);
        float d2 = t1 + ce;
        unsigned u = __float_as_uint(d2);
        u = (u & 0x80000000u) ? ~u : (u | 0x80000000u);
        ull key = ((ull)u << 32) | (ull)(unsigned)j;
        #pragma unroll
        for (int o = 16; o; o >>= 1) {
            ull other = __shfl_down_sync(0xffffffffu, key, o);
            if (other < key) key = other;
        }
        if ((tid & 31) == 0) wmin[m][tid >> 5] = key;
    }
    __syncthreads();

    if (tid < 32) {
        ull best = wmin[tid][0];
        #pragma unroll
        for (int t = 1; t < 8; t++) if (wmin[tid][t] < best) best = wmin[tid][t];
        int id = (int)(best & 0xffu);
        idxs[tid] = id;
        out[OFF_IDX + (size_t)(i0 + tid) * NQ + q] = (float)id;
    }
    __syncthreads();

    const float* cb = CB + (size_t)q * NE * DIM;
    float ssq = 0.f;
    #pragma unroll 4
    for (int m = 0; m < 32; m++) {
        float cv = cb[(size_t)idxs[m] * DIM + tid];
        float nr = rs[m][tid] - cv;
        size_t go = (size_t)(i0 + m) * DIM + tid;
        g_RES[go] = nr;
        out[go] = first ? cv : (out[go] + cv);
        ssq += nr * nr;
    }
    float st = blockReduceSum256(ssq, sbuf);
    if (tid == 0) atomicAdd(&g_VQ[q], st);
}

__global__ void k_vqmean(float* __restrict__ out) {
    if (threadIdx.x == 0) {
        float s = g_VQ[0] + g_VQ[1] + g_VQ[2] + g_VQ[3];
        out[OFF_MEAN] = s * (1.25f / (4.f * (float)NROWS * (float)DIM));
    }
}

// ---------------- launch ----------------
extern "C" void kernel_launch(void* const* d_in, const int* in_sizes, int n_in,
                              void* d_out, int out_size) {
    const float* x  = (const float*)d_in[0];
    const float* cb = (const float*)d_in[1];
    const int*   p1 = (const int*)d_in[2];
    const int*   p2 = (const int*)d_in[3];
    float* out = (float*)d_out;

    cudaFuncSetAttribute(k_lse_mma, cudaFuncAttributeMaxDynamicSharedMemorySize, 65536);

    k_init<<<NROWS * DIM / 4 / 256, 256>>>(x);
    k_prep<<<dim3(NE, NQ), 256>>>(cb);
    for (int q = 0; q < NQ; q++) {
        k_norm<<<NROWS, 256>>>();
        k_gather<<<KP, 256>>>(p1, p2);
        k_lse_mma<<<dim3(NROWS / 128, KP / 128), 256, 65536>>>();
        k_outer<<<1, 256>>>(out, q);
        k_quant<<<NROWS / 32, 256>>>(cb, out, q, q == 0);
    }
    k_vqmean<<<1, 32>>>(out);
}

// round 10
// speedup vs baseline: 1.1806x; 1.1806x over previous
#include <cuda_runtime.h>
#include <cuda_fp16.h>

#define NROWS 32768
#define DIM   256
#define NE    256
#define NQ    4
#define KP    4096

#define OFF_MEAN  (NROWS*DIM)            // 8388608
#define OFF_OUTER (NROWS*DIM + 1)
#define OFF_IDX   (NROWS*DIM + 1 + NQ)   // 8388613

typedef unsigned long long ull;
typedef unsigned int uint;

// ---------------- device scratch (no allocs allowed) ----------------
__device__ float  g_RES[NROWS*DIM];     // current residual
__device__ float  g_XN [NROWS*DIM];     // normalized residual (fp32)
__device__ float  g_RR [NROWS];         // ||residual||^2 per row
__device__ float2 g_CTP[NQ*128*NE];     // codebook, d-paired + transposed
__device__ float  g_CE [NQ*NE];         // ||e||^2
__device__ float  g_SEXP[KP];           // sum of exp(sim) per pair
__device__ float  g_POS [KP];           // pos logits
__device__ float  g_VQ  [NQ];           // sum of squared new residual
// fp16 row-major copies (16B aligned via uint4), 512B/row
__device__ uint4  g_XNB4[NROWS*DIM/8];  // keys  [32768][256] f16
__device__ uint4  g_QB4 [KP*DIM/8];     // queries [4096][256] f16

// ---------------- helpers ----------------
__device__ __forceinline__ ull bc2(float a) {
    ull r; asm("mov.b64 %0, {%1, %1};" : "=l"(r) : "f"(a)); return r;
}
__device__ __forceinline__ float2 u2f(ull u) {
    float2 f;
    f.x = __uint_as_float((unsigned)(u & 0xffffffffu));
    f.y = __uint_as_float((unsigned)(u >> 32));
    return f;
}
__device__ __forceinline__ void fma2(ull &acc, ull a, ull b) {
    asm("fma.rn.f32x2 %0, %1, %2, %0;" : "+l"(acc) : "l"(a), "l"(b));
}
__device__ __forceinline__ uint smem_u32(const void* p) {
    return (uint)__cvta_generic_to_shared(p);
}
// pack two fp32 -> f16x2 (lo = a, hi = b)
__device__ __forceinline__ uint pack_f16(float a, float b) {
    uint r; asm("cvt.rn.f16x2.f32 %0, %1, %2;" : "=r"(r) : "f"(b), "f"(a));
    return r;
}
__device__ __forceinline__ void cp16(uint dst, const void* src) {
    asm volatile("cp.async.cg.shared.global [%0], [%1], 16;"
                 :: "r"(dst), "l"(src) : "memory");
}
__device__ __forceinline__ void ldm4(uint &r0, uint &r1, uint &r2, uint &r3, uint addr) {
    asm volatile("ldmatrix.sync.aligned.m8n8.x4.shared.b16 {%0,%1,%2,%3}, [%4];"
                 : "=r"(r0), "=r"(r1), "=r"(r2), "=r"(r3) : "r"(addr));
}
// f16 MMA with f16 accumulators (full-rate path)
__device__ __forceinline__ void mma_f16acc(uint* c, const uint* a, const uint* b) {
    asm volatile(
        "mma.sync.aligned.m16n8k16.row.col.f16.f16.f16.f16 "
        "{%0,%1}, {%2,%3,%4,%5}, {%6,%7}, {%0,%1};"
        : "+r"(c[0]), "+r"(c[1])
        : "r"(a[0]), "r"(a[1]), "r"(a[2]), "r"(a[3]), "r"(b[0]), "r"(b[1]));
}
// LDS.128 -> two 64-bit regs
__device__ __forceinline__ void lds2x64(ull &u0, ull &u1, uint addr) {
    asm volatile("ld.shared.v2.b64 {%0,%1}, [%2];" : "=l"(u0), "=l"(u1) : "r"(addr));
}

// block reduce (256 threads), result valid on thread 0
__device__ __forceinline__ float blockReduceSum256(float v, float* sbuf) {
    #pragma unroll
    for (int o = 16; o; o >>= 1) v += __shfl_down_sync(0xffffffffu, v, o);
    int w = threadIdx.x >> 5, l = threadIdx.x & 31;
    if (l == 0) sbuf[w] = v;
    __syncthreads();
    if (w == 0) {
        v = (l < 8) ? sbuf[l] : 0.f;
        #pragma unroll
        for (int o = 4; o; o >>= 1) v += __shfl_down_sync(0xffffffffu, v, o);
    }
    return v;
}

// ---------------- kernels ----------------

__global__ void k_init(const float* __restrict__ x) {
    int i = blockIdx.x * 256 + threadIdx.x;
    ((float4*)g_RES)[i] = ((const float4*)x)[i];
    if (i < NQ) g_VQ[i] = 0.f;
}

__global__ void k_prep(const float* __restrict__ CB) {
    __shared__ float sbuf[8];
    int q = blockIdx.y, j = blockIdx.x, d = threadIdx.x;
    const float* row = CB + ((size_t)q * NE + j) * DIM;
    float v = row[d];
    float s = blockReduceSum256(v * v, sbuf);
    if (d == 0) g_CE[q * NE + j] = s;
    if (d < 128) {
        float2 p; p.x = row[2*d]; p.y = row[2*d + 1];
        g_CTP[(q * 128 + d) * NE + j] = p;
    }
}

// normalize row; write fp32 XN and fp16 row-major copy
__global__ void k_norm() {
    __shared__ float sbuf[8];
    __shared__ float stot;
    __shared__ float rowv[DIM];
    int row = blockIdx.x, d = threadIdx.x;
    float v = g_RES[(size_t)row * DIM + d];
    float s = blockReduceSum256(v * v, sbuf);
    if (d == 0) { stot = s; g_RR[row] = s; }
    __syncthreads();
    float inv = rsqrtf(stot + 1e-12f);
    float xv = v * inv;
    g_XN[(size_t)row * DIM + d] = xv;
    rowv[d] = xv;
    __syncthreads();
    if (d < 128)
        ((uint*)g_XNB4)[(size_t)row * 128 + d] = pack_f16(rowv[2*d], rowv[2*d + 1]);
}

// gather queries -> fp16 row-major, compute pos (fp32), zero SEXP
__global__ void k_gather(const int* __restrict__ p1, const int* __restrict__ p2) {
    __shared__ float sbuf[8];
    __shared__ float rowv[DIM];
    int k = blockIdx.x, d = threadIdx.x;
    int i1 = p1[k], i2 = p2[k];
    float a = g_XN[(size_t)i1 * DIM + d];
    float b = g_XN[(size_t)i2 * DIM + d];
    rowv[d] = a;
    float s = blockReduceSum256(a * b, sbuf);
    if (d == 0) { g_POS[k] = s * 10.f; g_SEXP[k] = 0.f; }
    __syncthreads();
    if (d < 128)
        ((uint*)g_QB4)[(size_t)k * 128 + d] = pack_f16(rowv[2*d], rowv[2*d + 1]);
}

// ---------------- f16 MMA LSE GEMM ----------------
// CTA: 128 pairs x 128 keys x K=256 f16, f16 accum.
// 8 warps as 2(m) x 4(n); warp tile 64x32 = 4x4 m16n8k16.
// K chunks of 64, double-buffered cp.async, XOR-swizzled smem.
__global__ void __launch_bounds__(256, 2) k_lse_mma() {
    extern __shared__ char dyn[];
    uint sbase = smem_u32(dyn);

    int tid  = threadIdx.x;
    int wid  = tid >> 5, lane = tid & 31;
    int wm   = wid >> 2, wn   = wid & 3;
    int bn   = blockIdx.x, bm = blockIdx.y;

    const char* gA = (const char*)g_QB4  + (size_t)(bm * 128) * 512;
    const char* gB = (const char*)g_XNB4 + (size_t)(bn * 128) * 512;

    uint acc[4][4][2];
    #pragma unroll
    for (int mt = 0; mt < 4; mt++)
        #pragma unroll
        for (int nt = 0; nt < 4; nt++) { acc[mt][nt][0] = 0u; acc[mt][nt][1] = 0u; }

    // chunk loader: 128 rows x 64 f16 (128B/row) for A and B into buffer b
    auto load_chunk = [&](int kc, int b) {
        uint abuf = sbase + (uint)b * 32768u;
        uint bbuf = abuf + 16384u;
        #pragma unroll
        for (int t = 0; t < 4; t++) {
            int i = tid + t * 256;          // 0..1023
            int row = i >> 3, c = i & 7;
            uint soff = (uint)((row * 8 + (c ^ (row & 7))) * 16);
            cp16(abuf + soff, gA + (size_t)row * 512 + kc * 128 + c * 16);
            cp16(bbuf + soff, gB + (size_t)row * 512 + kc * 128 + c * 16);
        }
    };

    load_chunk(0, 0);
    asm volatile("cp.async.commit_group;" ::: "memory");
    load_chunk(1, 1);
    asm volatile("cp.async.commit_group;" ::: "memory");

    #pragma unroll
    for (int kc = 0; kc < 4; kc++) {
        if (kc < 3) asm volatile("cp.async.wait_group 1;" ::: "memory");
        else        asm volatile("cp.async.wait_group 0;" ::: "memory");
        __syncthreads();

        uint abuf = sbase + (uint)(kc & 1) * 32768u;
        uint bbuf = abuf + 16384u;

        #pragma unroll
        for (int ks = 0; ks < 4; ks++) {
            uint afr[4][4];
            #pragma unroll
            for (int mt = 0; mt < 4; mt++) {
                int row = wm * 64 + mt * 16 + (lane & 15);
                int chunk = ks * 2 + (lane >> 4);
                uint addr = abuf + (uint)((row * 8 + (chunk ^ (row & 7))) * 16);
                ldm4(afr[mt][0], afr[mt][1], afr[mt][2], afr[mt][3], addr);
            }
            uint bfr[4][2];
            #pragma unroll
            for (int p = 0; p < 2; p++) {
                int g = lane >> 3;
                int ntl = 2 * p + (g >> 1);
                int row = wn * 32 + ntl * 8 + (lane & 7);
                int chunk = ks * 2 + (g & 1);
                uint addr = bbuf + (uint)((row * 8 + (chunk ^ (row & 7))) * 16);
                ldm4(bfr[2*p][0], bfr[2*p][1], bfr[2*p+1][0], bfr[2*p+1][1], addr);
            }
            #pragma unroll
            for (int mt = 0; mt < 4; mt++)
                #pragma unroll
                for (int nt = 0; nt < 4; nt++)
                    mma_f16acc(acc[mt][nt], afr[mt], bfr[nt]);
        }
        __syncthreads();
        if (kc < 2) {
            load_chunk(kc + 2, kc & 1);
            asm volatile("cp.async.commit_group;" ::: "memory");
        }
    }

    // epilogue: exp(10*acc) + row sums. rows: wm*64 + mt*16 + lane/4 (+8)
    float* red = (float*)dyn;   // 128 rows x 4 n-warps
    float s0[4], s1[4];
    #pragma unroll
    for (int mt = 0; mt < 4; mt++) {
        float a0 = 0.f, a1 = 0.f;
        #pragma unroll
        for (int nt = 0; nt < 4; nt++) {
            float2 f0 = __half22float2(*(const __half2*)&acc[mt][nt][0]);
            float2 f1 = __half22float2(*(const __half2*)&acc[mt][nt][1]);
            a0 += __expf(10.f * f0.x) + __expf(10.f * f0.y);
            a1 += __expf(10.f * f1.x) + __expf(10.f * f1.y);
        }
        #pragma unroll
        for (int o = 1; o < 4; o <<= 1) {
            a0 += __shfl_xor_sync(0xffffffffu, a0, o);
            a1 += __shfl_xor_sync(0xffffffffu, a1, o);
        }
        s0[mt] = a0; s1[mt] = a1;
    }
    __syncthreads();           // all warps done with smem buffers
    if ((lane & 3) == 0) {
        int rbase = wm * 64 + (lane >> 2);
        #pragma unroll
        for (int mt = 0; mt < 4; mt++) {
            red[(rbase + mt * 16)     * 4 + wn] = s0[mt];
            red[(rbase + mt * 16 + 8) * 4 + wn] = s1[mt];
        }
    }
    __syncthreads();
    if (tid < 128) {
        float s = red[tid * 4] + red[tid * 4 + 1] + red[tid * 4 + 2] + red[tid * 4 + 3];
        atomicAdd(&g_SEXP[bm * 128 + tid], s);
    }
}

__global__ void k_outer(float* __restrict__ out, int q) {
    __shared__ float sbuf[8];
    float acc = 0.f;
    for (int k = threadIdx.x; k < KP; k += 256)
        acc += logf(g_SEXP[k]) - g_POS[k];
    float s = blockReduceSum256(acc, sbuf);
    if (threadIdx.x == 0) out[OFF_OUTER + q] = s / (float)KP;
}

// quantize (reference-rounding-matched distances, fp32).
// LDS.128 (ld.shared.v2.b64) halves shared-memory wavefronts vs b64 loads.
__global__ void __launch_bounds__(256) k_quant(const float* __restrict__ CB,
                                               float* __restrict__ out,
                                               int q, int first) {
    __shared__ __align__(16) float rs[32][DIM];
    __shared__ ull   wmin[32][8];
    __shared__ int   idxs[32];
    __shared__ float sbuf[8];
    __shared__ float rr_s[32];

    int tid = threadIdx.x;
    int i0 = blockIdx.x * 32;

    #pragma unroll
    for (int i = 0; i < 8; i++) {
        int lin = tid + i * 256;
        int m = lin >> 6, c = lin & 63;
        ((float4*)&rs[m][0])[c] = *(const float4*)(g_RES + (size_t)(i0 + m) * DIM + c * 4);
    }
    if (tid < 32) rr_s[tid] = g_RR[i0 + tid];
    __syncthreads();

    int j = tid;
    uint rs_base = smem_u32(&rs[0][0]);
    ull dot2[32];
    #pragma unroll
    for (int m = 0; m < 32; m++) dot2[m] = 0ull;

    const float2* ctp = g_CTP + (size_t)q * 128 * NE;
    #pragma unroll 2
    for (int dpc = 0; dpc < 32; dpc++) {
        ull ct[4];
        #pragma unroll
        for (int c = 0; c < 4; c++)
            ct[c] = *(const ull*)&ctp[(dpc * 4 + c) * NE + j];
        #pragma unroll
        for (int m = 0; m < 32; m++) {
            uint addr = rs_base + (uint)(m * 1024 + dpc * 32);
            ull r0, r1, r2, r3;
            lds2x64(r0, r1, addr);
            lds2x64(r2, r3, addr + 16u);
            fma2(dot2[m], r0, ct[0]);
            fma2(dot2[m], r1, ct[1]);
            fma2(dot2[m], r2, ct[2]);
            fma2(dot2[m], r3, ct[3]);
        }
    }

    float ce = g_CE[q * NE + j];
    #pragma unroll
    for (int m = 0; m < 32; m++) {
        float2 f = u2f(dot2[m]);
        float dotv = f.x + f.y;
        float t1 = fmaf(-2.f, dotv, rr_s[m]);
        float d2 = t1 + ce;
        unsigned u = __float_as_uint(d2);
        u = (u & 0x80000000u) ? ~u : (u | 0x80000000u);
        ull key = ((ull)u << 32) | (ull)(unsigned)j;
        #pragma unroll
        for (int o = 16; o; o >>= 1) {
            ull other = __shfl_down_sync(0xffffffffu, key, o);
            if (other < key) key = other;
        }
        if ((tid & 31) == 0) wmin[m][tid >> 5] = key;
    }
    __syncthreads();

    if (tid < 32) {
        ull best = wmin[tid][0];
        #pragma unroll
        for (int t = 1; t < 8; t++) if (wmin[tid][t] < best) best = wmin[tid][t];
        int id = (int)(best & 0xffu);
        idxs[tid] = id;
        out[OFF_IDX + (size_t)(i0 + tid) * NQ + q] = (float)id;
    }
    __syncthreads();

    const float* cb = CB + (size_t)q * NE * DIM;
    float ssq = 0.f;
    #pragma unroll 4
    for (int m = 0; m < 32; m++) {
        float cv = cb[(size_t)idxs[m] * DIM + tid];
        float nr = rs[m][tid] - cv;
        size_t go = (size_t)(i0 + m) * DIM + tid;
        g_RES[go] = nr;
        out[go] = first ? cv : (out[go] + cv);
        ssq += nr * nr;
    }
    float st = blockReduceSum256(ssq, sbuf);
    if (tid == 0) atomicAdd(&g_VQ[q], st);
}

__global__ void k_vqmean(float* __restrict__ out) {
    if (threadIdx.x == 0) {
        float s = g_VQ[0] + g_VQ[1] + g_VQ[2] + g_VQ[3];
        out[OFF_MEAN] = s * (1.25f / (4.f * (float)NROWS * (float)DIM));
    }
}

// ---------------- launch ----------------
extern "C" void kernel_launch(void* const* d_in, const int* in_sizes, int n_in,
                              void* d_out, int out_size) {
    const float* x  = (const float*)d_in[0];
    const float* cb = (const float*)d_in[1];
    const int*   p1 = (const int*)d_in[2];
    const int*   p2 = (const int*)d_in[3];
    float* out = (float*)d_out;

    cudaFuncSetAttribute(k_lse_mma, cudaFuncAttributeMaxDynamicSharedMemorySize, 65536);

    k_init<<<NROWS * DIM / 4 / 256, 256>>>(x);
    k_prep<<<dim3(NE, NQ), 256>>>(cb);
    for (int q = 0; q < NQ; q++) {
        k_norm<<<NROWS, 256>>>();
        k_gather<<<KP, 256>>>(p1, p2);
        k_lse_mma<<<dim3(NROWS / 128, KP / 128), 256, 65536>>>();
        k_outer<<<1, 256>>>(out, q);
        k_quant<<<NROWS / 32, 256>>>(cb, out, q, q == 0);
    }
    k_vqmean<<<1, 32>>>(out);
}

// round 11
// speedup vs baseline: 1.1894x; 1.0075x over previous
#include <cuda_runtime.h>
#include <cuda_fp16.h>

#define NROWS 32768
#define DIM   256
#define NE    256
#define NQ    4
#define KP    4096

#define OFF_MEAN  (NROWS*DIM)            // 8388608
#define OFF_OUTER (NROWS*DIM + 1)
#define OFF_IDX   (NROWS*DIM + 1 + NQ)   // 8388613

typedef unsigned long long ull;
typedef unsigned int uint;

// ---------------- device scratch (no allocs allowed) ----------------
__device__ float  g_RES[NROWS*DIM];     // current residual
__device__ float  g_XN [NROWS*DIM];     // normalized residual (fp32)
__device__ float  g_RR [NROWS];         // ||residual||^2 per row
__device__ float2 g_CTP[NQ*128*NE];     // codebook, d-paired + transposed
__device__ float  g_CE [NQ*NE];         // ||e||^2
__device__ float  g_SEXP[KP];           // sum of exp(sim) per pair
__device__ float  g_POS [KP];           // pos logits
__device__ float  g_VQ  [NQ];           // sum of squared new residual
// fp16 row-major copies (16B aligned via uint4), 512B/row
__device__ uint4  g_XNB4[NROWS*DIM/8];  // keys  [32768][256] f16
__device__ uint4  g_QB4 [KP*DIM/8];     // queries [4096][256] f16

// ---------------- helpers ----------------
__device__ __forceinline__ float2 u2f(ull u) {
    float2 f;
    f.x = __uint_as_float((unsigned)(u & 0xffffffffu));
    f.y = __uint_as_float((unsigned)(u >> 32));
    return f;
}
__device__ __forceinline__ void fma2(ull &acc, ull a, ull b) {
    asm("fma.rn.f32x2 %0, %1, %2, %0;" : "+l"(acc) : "l"(a), "l"(b));
}
__device__ __forceinline__ uint smem_u32(const void* p) {
    return (uint)__cvta_generic_to_shared(p);
}
// pack two fp32 -> f16x2 (lo = a, hi = b)
__device__ __forceinline__ uint pack_f16(float a, float b) {
    uint r; asm("cvt.rn.f16x2.f32 %0, %1, %2;" : "=r"(r) : "f"(b), "f"(a));
    return r;
}
__device__ __forceinline__ void cp16(uint dst, const void* src) {
    asm volatile("cp.async.cg.shared.global [%0], [%1], 16;"
                 :: "r"(dst), "l"(src) : "memory");
}
__device__ __forceinline__ void ldm4(uint &r0, uint &r1, uint &r2, uint &r3, uint addr) {
    asm volatile("ldmatrix.sync.aligned.m8n8.x4.shared.b16 {%0,%1,%2,%3}, [%4];"
                 : "=r"(r0), "=r"(r1), "=r"(r2), "=r"(r3) : "r"(addr));
}
// f16 MMA with f16 accumulators
__device__ __forceinline__ void mma_f16acc(uint* c, const uint* a, const uint* b) {
    asm volatile(
        "mma.sync.aligned.m16n8k16.row.col.f16.f16.f16.f16 "
        "{%0,%1}, {%2,%3,%4,%5}, {%6,%7}, {%0,%1};"
        : "+r"(c[0]), "+r"(c[1])
        : "r"(a[0]), "r"(a[1]), "r"(a[2]), "r"(a[3]), "r"(b[0]), "r"(b[1]));
}
// LDS.128 -> two 64-bit regs
__device__ __forceinline__ void lds2x64(ull &u0, ull &u1, uint addr) {
    asm volatile("ld.shared.v2.b64 {%0,%1}, [%2];" : "=l"(u0), "=l"(u1) : "r"(addr));
}

// block reduce (256 threads), result valid on thread 0
__device__ __forceinline__ float blockReduceSum256(float v, float* sbuf) {
    #pragma unroll
    for (int o = 16; o; o >>= 1) v += __shfl_down_sync(0xffffffffu, v, o);
    int w = threadIdx.x >> 5, l = threadIdx.x & 31;
    if (l == 0) sbuf[w] = v;
    __syncthreads();
    if (w == 0) {
        v = (l < 8) ? sbuf[l] : 0.f;
        #pragma unroll
        for (int o = 4; o; o >>= 1) v += __shfl_down_sync(0xffffffffu, v, o);
    }
    return v;
}

// ---------------- kernels ----------------

__global__ void k_init(const float* __restrict__ x) {
    int i = blockIdx.x * 256 + threadIdx.x;
    ((float4*)g_RES)[i] = ((const float4*)x)[i];
    if (i < NQ) g_VQ[i] = 0.f;
}

__global__ void k_prep(const float* __restrict__ CB) {
    __shared__ float sbuf[8];
    int q = blockIdx.y, j = blockIdx.x, d = threadIdx.x;
    const float* row = CB + ((size_t)q * NE + j) * DIM;
    float v = row[d];
    float s = blockReduceSum256(v * v, sbuf);
    if (d == 0) g_CE[q * NE + j] = s;
    if (d < 128) {
        float2 p; p.x = row[2*d]; p.y = row[2*d + 1];
        g_CTP[(q * 128 + d) * NE + j] = p;
    }
}

// normalize row; write fp32 XN and fp16 row-major copy (stage 0 only)
__global__ void k_norm() {
    __shared__ float sbuf[8];
    __shared__ float stot;
    __shared__ float rowv[DIM];
    int row = blockIdx.x, d = threadIdx.x;
    float v = g_RES[(size_t)row * DIM + d];
    float s = blockReduceSum256(v * v, sbuf);
    if (d == 0) { stot = s; g_RR[row] = s; }
    __syncthreads();
    float inv = rsqrtf(stot + 1e-12f);
    float xv = v * inv;
    g_XN[(size_t)row * DIM + d] = xv;
    rowv[d] = xv;
    __syncthreads();
    if (d < 128)
        ((uint*)g_XNB4)[(size_t)row * 128 + d] = pack_f16(rowv[2*d], rowv[2*d + 1]);
}

// gather queries -> fp16 row-major, compute pos (fp32), zero SEXP
__global__ void k_gather(const int* __restrict__ p1, const int* __restrict__ p2) {
    __shared__ float sbuf[8];
    __shared__ float rowv[DIM];
    int k = blockIdx.x, d = threadIdx.x;
    int i1 = p1[k], i2 = p2[k];
    float a = g_XN[(size_t)i1 * DIM + d];
    float b = g_XN[(size_t)i2 * DIM + d];
    rowv[d] = a;
    float s = blockReduceSum256(a * b, sbuf);
    if (d == 0) { g_POS[k] = s * 10.f; g_SEXP[k] = 0.f; }
    __syncthreads();
    if (d < 128)
        ((uint*)g_QB4)[(size_t)k * 128 + d] = pack_f16(rowv[2*d], rowv[2*d + 1]);
}

// ---------------- f16 MMA LSE GEMM ----------------
// CTA: 128 pairs x 128 keys x K=256 f16, f16 accum.
// 8 warps as 2(m) x 4(n); warp tile 64x32 = 4x4 m16n8k16.
// K chunks of 64, double-buffered cp.async, XOR-swizzled smem.
// Fragment double-buffering: ldmatrix for k-step s+1 issued before MMAs of s.
__global__ void __launch_bounds__(256, 2) k_lse_mma() {
    extern __shared__ char dyn[];
    uint sbase = smem_u32(dyn);

    int tid  = threadIdx.x;
    int wid  = tid >> 5, lane = tid & 31;
    int wm   = wid >> 2, wn   = wid & 3;
    int bn   = blockIdx.x, bm = blockIdx.y;

    const char* gA = (const char*)g_QB4  + (size_t)(bm * 128) * 512;
    const char* gB = (const char*)g_XNB4 + (size_t)(bn * 128) * 512;

    uint acc[4][4][2];
    #pragma unroll
    for (int mt = 0; mt < 4; mt++)
        #pragma unroll
        for (int nt = 0; nt < 4; nt++) { acc[mt][nt][0] = 0u; acc[mt][nt][1] = 0u; }

    // chunk loader: 128 rows x 64 f16 (128B/row) for A and B into buffer b
    auto load_chunk = [&](int kc, int b) {
        uint abuf = sbase + (uint)b * 32768u;
        uint bbuf = abuf + 16384u;
        #pragma unroll
        for (int t = 0; t < 4; t++) {
            int i = tid + t * 256;          // 0..1023
            int row = i >> 3, c = i & 7;
            uint soff = (uint)((row * 8 + (c ^ (row & 7))) * 16);
            cp16(abuf + soff, gA + (size_t)row * 512 + kc * 128 + c * 16);
            cp16(bbuf + soff, gB + (size_t)row * 512 + kc * 128 + c * 16);
        }
    };

    // fragment loader for one k16 step
    auto ldfrag = [&](uint abuf, uint bbuf, int ks, uint afr[4][4], uint bfr[4][2]) {
        #pragma unroll
        for (int mt = 0; mt < 4; mt++) {
            int row = wm * 64 + mt * 16 + (lane & 15);
            int chunk = ks * 2 + (lane >> 4);
            uint addr = abuf + (uint)((row * 8 + (chunk ^ (row & 7))) * 16);
            ldm4(afr[mt][0], afr[mt][1], afr[mt][2], afr[mt][3], addr);
        }
        #pragma unroll
        for (int p = 0; p < 2; p++) {
            int g = lane >> 3;
            int ntl = 2 * p + (g >> 1);
            int row = wn * 32 + ntl * 8 + (lane & 7);
            int chunk = ks * 2 + (g & 1);
            uint addr = bbuf + (uint)((row * 8 + (chunk ^ (row & 7))) * 16);
            ldm4(bfr[2*p][0], bfr[2*p][1], bfr[2*p+1][0], bfr[2*p+1][1], addr);
        }
    };

    load_chunk(0, 0);
    asm volatile("cp.async.commit_group;" ::: "memory");
    load_chunk(1, 1);
    asm volatile("cp.async.commit_group;" ::: "memory");

    #pragma unroll
    for (int kc = 0; kc < 4; kc++) {
        if (kc < 3) asm volatile("cp.async.wait_group 1;" ::: "memory");
        else        asm volatile("cp.async.wait_group 0;" ::: "memory");
        __syncthreads();

        uint abuf = sbase + (uint)(kc & 1) * 32768u;
        uint bbuf = abuf + 16384u;

        uint afr[2][4][4];
        uint bfr[2][4][2];
        ldfrag(abuf, bbuf, 0, afr[0], bfr[0]);

        #pragma unroll
        for (int ks = 0; ks < 4; ks++) {
            int cur = ks & 1;
            if (ks < 3) ldfrag(abuf, bbuf, ks + 1, afr[cur ^ 1], bfr[cur ^ 1]);
            #pragma unroll
            for (int mt = 0; mt < 4; mt++)
                #pragma unroll
                for (int nt = 0; nt < 4; nt++)
                    mma_f16acc(acc[mt][nt], afr[cur][mt], bfr[cur][nt]);
        }
        __syncthreads();
        if (kc < 2) {
            load_chunk(kc + 2, kc & 1);
            asm volatile("cp.async.commit_group;" ::: "memory");
        }
    }

    // epilogue: exp(10*acc) + row sums. rows: wm*64 + mt*16 + lane/4 (+8)
    float* red = (float*)dyn;   // 128 rows x 4 n-warps
    float s0[4], s1[4];
    #pragma unroll
    for (int mt = 0; mt < 4; mt++) {
        float a0 = 0.f, a1 = 0.f;
        #pragma unroll
        for (int nt = 0; nt < 4; nt++) {
            float2 f0 = __half22float2(*(const __half2*)&acc[mt][nt][0]);
            float2 f1 = __half22float2(*(const __half2*)&acc[mt][nt][1]);
            a0 += __expf(10.f * f0.x) + __expf(10.f * f0.y);
            a1 += __expf(10.f * f1.x) + __expf(10.f * f1.y);
        }
        #pragma unroll
        for (int o = 1; o < 4; o <<= 1) {
            a0 += __shfl_xor_sync(0xffffffffu, a0, o);
            a1 += __shfl_xor_sync(0xffffffffu, a1, o);
        }
        s0[mt] = a0; s1[mt] = a1;
    }
    __syncthreads();           // all warps done with smem buffers
    if ((lane & 3) == 0) {
        int rbase = wm * 64 + (lane >> 2);
        #pragma unroll
        for (int mt = 0; mt < 4; mt++) {
            red[(rbase + mt * 16)     * 4 + wn] = s0[mt];
            red[(rbase + mt * 16 + 8) * 4 + wn] = s1[mt];
        }
    }
    __syncthreads();
    if (tid < 128) {
        float s = red[tid * 4] + red[tid * 4 + 1] + red[tid * 4 + 2] + red[tid * 4 + 3];
        atomicAdd(&g_SEXP[bm * 128 + tid], s);
    }
}

__global__ void k_outer(float* __restrict__ out, int q) {
    __shared__ float sbuf[8];
    float acc = 0.f;
    for (int k = threadIdx.x; k < KP; k += 256)
        acc += logf(g_SEXP[k]) - g_POS[k];
    float s = blockReduceSum256(acc, sbuf);
    if (threadIdx.x == 0) out[OFF_OUTER + q] = s / (float)KP;
}

// quantize + FUSED next-stage normalize.
// Computes argmin (reference-rounding-matched fp32 d2), updates RES/x_q,
// then produces per-row ||nr||^2 (-> g_RR), XN fp32 and f16-packed copies for
// the NEXT stage -- eliminating the separate k_norm pass (rows are block-local).
__global__ void __launch_bounds__(256) k_quant(const float* __restrict__ CB,
                                               float* __restrict__ out,
                                               int q, int first, int last) {
    __shared__ __align__(16) float rs[32][DIM];
    __shared__ ull   wmin[32][8];
    __shared__ float rowsum[32][8];
    __shared__ int   idxs[32];
    __shared__ float rr_s[32];
    __shared__ float inv_s[32];

    int tid = threadIdx.x;
    int lane = tid & 31, w = tid >> 5;
    int i0 = blockIdx.x * 32;

    #pragma unroll
    for (int i = 0; i < 8; i++) {
        int lin = tid + i * 256;
        int m = lin >> 6, c = lin & 63;
        ((float4*)&rs[m][0])[c] = *(const float4*)(g_RES + (size_t)(i0 + m) * DIM + c * 4);
    }
    if (tid < 32) rr_s[tid] = g_RR[i0 + tid];
    __syncthreads();

    int j = tid;
    uint rs_base = smem_u32(&rs[0][0]);
    ull dot2[32];
    #pragma unroll
    for (int m = 0; m < 32; m++) dot2[m] = 0ull;

    const float2* ctp = g_CTP + (size_t)q * 128 * NE;
    #pragma unroll 2
    for (int dpc = 0; dpc < 32; dpc++) {
        ull ct[4];
        #pragma unroll
        for (int c = 0; c < 4; c++)
            ct[c] = *(const ull*)&ctp[(dpc * 4 + c) * NE + j];
        #pragma unroll
        for (int m = 0; m < 32; m++) {
            uint addr = rs_base + (uint)(m * 1024 + dpc * 32);
            ull r0, r1, r2, r3;
            lds2x64(r0, r1, addr);
            lds2x64(r2, r3, addr + 16u);
            fma2(dot2[m], r0, ct[0]);
            fma2(dot2[m], r1, ct[1]);
            fma2(dot2[m], r2, ct[2]);
            fma2(dot2[m], r3, ct[3]);
        }
    }

    float ce = g_CE[q * NE + j];
    #pragma unroll
    for (int m = 0; m < 32; m++) {
        float2 f = u2f(dot2[m]);
        float dotv = f.x + f.y;
        float t1 = fmaf(-2.f, dotv, rr_s[m]);
        float d2 = t1 + ce;
        unsigned u = __float_as_uint(d2);
        u = (u & 0x80000000u) ? ~u : (u | 0x80000000u);
        ull key = ((ull)u << 32) | (ull)(unsigned)j;
        #pragma unroll
        for (int o = 16; o; o >>= 1) {
            ull other = __shfl_down_sync(0xffffffffu, key, o);
            if (other < key) key = other;
        }
        if (lane == 0) wmin[m][w] = key;
    }
    __syncthreads();

    if (tid < 32) {
        ull best = wmin[tid][0];
        #pragma unroll
        for (int t = 1; t < 8; t++) if (wmin[tid][t] < best) best = wmin[tid][t];
        int id = (int)(best & 0xffu);
        idxs[tid] = id;
        out[OFF_IDX + (size_t)(i0 + tid) * NQ + q] = (float)id;
    }
    __syncthreads();

    // residual / x_q update + per-row squared sums (each (m,tid) slot exclusive)
    const float* cb = CB + (size_t)q * NE * DIM;
    #pragma unroll 4
    for (int m = 0; m < 32; m++) {
        float cv = cb[(size_t)idxs[m] * DIM + tid];
        float nr = rs[m][tid] - cv;
        size_t go = (size_t)(i0 + m) * DIM + tid;
        g_RES[go] = nr;
        out[go] = first ? cv : (out[go] + cv);
        rs[m][tid] = nr;                  // overwrite with new residual
        float v = nr * nr;
        #pragma unroll
        for (int o = 16; o; o >>= 1) v += __shfl_down_sync(0xffffffffu, v, o);
        if (lane == 0) rowsum[m][w] = v;
    }
    __syncthreads();

    if (tid < 32) {
        float rr = 0.f;
        #pragma unroll
        for (int t = 0; t < 8; t++) rr += rowsum[tid][t];
        rr_s[tid] = rr;                   // reuse as new-RR stash
        inv_s[tid] = rsqrtf(rr + 1e-12f);
        if (!last) g_RR[i0 + tid] = rr;
    }
    __syncthreads();

    if (tid == 0) {
        float s = 0.f;
        #pragma unroll
        for (int m = 0; m < 32; m++) s += rr_s[m];
        atomicAdd(&g_VQ[q], s);
    }

    if (!last) {
        // write XN fp32 (float4) and f16-packed copy for next stage
        #pragma unroll
        for (int i = 0; i < 8; i++) {
            int lin = tid + i * 256;
            int m = lin >> 6, c = lin & 63;
            float inv = inv_s[m];
            float4 v = ((const float4*)&rs[m][0])[c];
            v.x *= inv; v.y *= inv; v.z *= inv; v.w *= inv;
            *(float4*)(g_XN + (size_t)(i0 + m) * DIM + c * 4) = v;
        }
        #pragma unroll
        for (int i = 0; i < 4; i++) {
            int lin = tid + i * 256;
            int m = lin >> 5, c = lin & 31;     // 32 uint4 per row
            float inv = inv_s[m];
            const float* r = &rs[m][c * 8];
            uint4 p;
            p.x = pack_f16(r[0]*inv, r[1]*inv);
            p.y = pack_f16(r[2]*inv, r[3]*inv);
            p.z = pack_f16(r[4]*inv, r[5]*inv);
            p.w = pack_f16(r[6]*inv, r[7]*inv);
            g_XNB4[(size_t)(i0 + m) * 32 + c] = p;
        }
    }
}

__global__ void k_vqmean(float* __restrict__ out) {
    if (threadIdx.x == 0) {
        float s = g_VQ[0] + g_VQ[1] + g_VQ[2] + g_VQ[3];
        out[OFF_MEAN] = s * (1.25f / (4.f * (float)NROWS * (float)DIM));
    }
}

// ---------------- launch ----------------
extern "C" void kernel_launch(void* const* d_in, const int* in_sizes, int n_in,
                              void* d_out, int out_size) {
    const float* x  = (const float*)d_in[0];
    const float* cb = (const float*)d_in[1];
    const int*   p1 = (const int*)d_in[2];
    const int*   p2 = (const int*)d_in[3];
    float* out = (float*)d_out;

    cudaFuncSetAttribute(k_lse_mma, cudaFuncAttributeMaxDynamicSharedMemorySize, 65536);

    k_init<<<NROWS * DIM / 4 / 256, 256>>>(x);
    k_prep<<<dim3(NE, NQ), 256>>>(cb);
    for (int q = 0; q < NQ; q++) {
        if (q == 0) k_norm<<<NROWS, 256>>>();
        k_gather<<<KP, 256>>>(p1, p2);
        k_lse_mma<<<dim3(NROWS / 128, KP / 128), 256, 65536>>>();
        k_outer<<<1, 256>>>(out, q);
        k_quant<<<NROWS / 32, 256>>>(cb, out, q, q == 0, q == NQ - 1);
    }
    k_vqmean<<<1, 32>>>(out);
}

// round 12
// speedup vs baseline: 1.1910x; 1.0013x over previous
#include <cuda_runtime.h>
#include <cuda_fp16.h>

#define NROWS 32768
#define DIM   256
#define NE    256
#define NQ    4
#define KP    4096

#define OFF_MEAN  (NROWS*DIM)            // 8388608
#define OFF_OUTER (NROWS*DIM + 1)
#define OFF_IDX   (NROWS*DIM + 1 + NQ)   // 8388613

#define LSE_BLOCKS  8192                 // (NROWS/128) * (KP/128)
#define QUANT_BLOCKS 1024                // NROWS/32

typedef unsigned long long ull;
typedef unsigned int uint;

// ---------------- device scratch (no allocs allowed) ----------------
__device__ float  g_RES[NROWS*DIM];         // current residual
__device__ float  g_XN [2][NROWS*DIM];      // normalized residual, stage-parity buffers
__device__ float  g_RR [NROWS];             // ||residual||^2 per row
__device__ float2 g_CTP[NQ*128*NE];         // codebook, d-paired + transposed
__device__ float  g_CE [NQ*NE];             // ||e||^2
__device__ float  g_SEXP[KP];               // sum of exp(sim) per pair
__device__ float  g_POS [KP];               // pos logits
__device__ float  g_VQ  [NQ];               // sum of squared new residual
// fp16 row-major copies (16B aligned via uint4), 512B/row, stage-parity buffers
__device__ uint4  g_XNB4[2][NROWS*DIM/8];   // keys  [32768][256] f16
__device__ uint4  g_QB4 [KP*DIM/8];         // queries [4096][256] f16

// ---------------- helpers ----------------
__device__ __forceinline__ float2 u2f(ull u) {
    float2 f;
    f.x = __uint_as_float((unsigned)(u & 0xffffffffu));
    f.y = __uint_as_float((unsigned)(u >> 32));
    return f;
}
__device__ __forceinline__ void fma2(ull &acc, ull a, ull b) {
    asm("fma.rn.f32x2 %0, %1, %2, %0;" : "+l"(acc) : "l"(a), "l"(b));
}
__device__ __forceinline__ uint smem_u32(const void* p) {
    return (uint)__cvta_generic_to_shared(p);
}
__device__ __forceinline__ uint pack_f16(float a, float b) {
    uint r; asm("cvt.rn.f16x2.f32 %0, %1, %2;" : "=r"(r) : "f"(b), "f"(a));
    return r;
}
__device__ __forceinline__ void cp16(uint dst, const void* src) {
    asm volatile("cp.async.cg.shared.global [%0], [%1], 16;"
                 :: "r"(dst), "l"(src) : "memory");
}
__device__ __forceinline__ void ldm4(uint &r0, uint &r1, uint &r2, uint &r3, uint addr) {
    asm volatile("ldmatrix.sync.aligned.m8n8.x4.shared.b16 {%0,%1,%2,%3}, [%4];"
                 : "=r"(r0), "=r"(r1), "=r"(r2), "=r"(r3) : "r"(addr));
}
__device__ __forceinline__ void mma_f16acc(uint* c, const uint* a, const uint* b) {
    asm volatile(
        "mma.sync.aligned.m16n8k16.row.col.f16.f16.f16.f16 "
        "{%0,%1}, {%2,%3,%4,%5}, {%6,%7}, {%0,%1};"
        : "+r"(c[0]), "+r"(c[1])
        : "r"(a[0]), "r"(a[1]), "r"(a[2]), "r"(a[3]), "r"(b[0]), "r"(b[1]));
}
__device__ __forceinline__ void lds2x64(ull &u0, ull &u1, uint addr) {
    asm volatile("ld.shared.v2.b64 {%0,%1}, [%2];" : "=l"(u0), "=l"(u1) : "r"(addr));
}

__device__ __forceinline__ float blockReduceSum256(float v, float* sbuf) {
    #pragma unroll
    for (int o = 16; o; o >>= 1) v += __shfl_down_sync(0xffffffffu, v, o);
    int w = threadIdx.x >> 5, l = threadIdx.x & 31;
    if (l == 0) sbuf[w] = v;
    __syncthreads();
    if (w == 0) {
        v = (l < 8) ? sbuf[l] : 0.f;
        #pragma unroll
        for (int o = 4; o; o >>= 1) v += __shfl_down_sync(0xffffffffu, v, o);
    }
    return v;
}

// ---------------- small kernels ----------------

__global__ void k_init(const float* __restrict__ x) {
    int i = blockIdx.x * 256 + threadIdx.x;
    ((float4*)g_RES)[i] = ((const float4*)x)[i];
    if (i < NQ) g_VQ[i] = 0.f;
}

__global__ void k_prep(const float* __restrict__ CB) {
    __shared__ float sbuf[8];
    int q = blockIdx.y, j = blockIdx.x, d = threadIdx.x;
    const float* row = CB + ((size_t)q * NE + j) * DIM;
    float v = row[d];
    float s = blockReduceSum256(v * v, sbuf);
    if (d == 0) g_CE[q * NE + j] = s;
    if (d < 128) {
        float2 p; p.x = row[2*d]; p.y = row[2*d + 1];
        g_CTP[(q * 128 + d) * NE + j] = p;
    }
}

// stage-0 normalize into parity buffer 0
__global__ void k_norm() {
    __shared__ float sbuf[8];
    __shared__ float stot;
    __shared__ float rowv[DIM];
    int row = blockIdx.x, d = threadIdx.x;
    float v = g_RES[(size_t)row * DIM + d];
    float s = blockReduceSum256(v * v, sbuf);
    if (d == 0) { stot = s; g_RR[row] = s; }
    __syncthreads();
    float inv = rsqrtf(stot + 1e-12f);
    float xv = v * inv;
    g_XN[0][(size_t)row * DIM + d] = xv;
    rowv[d] = xv;
    __syncthreads();
    if (d < 128)
        ((uint*)g_XNB4[0])[(size_t)row * 128 + d] = pack_f16(rowv[2*d], rowv[2*d + 1]);
}

// gather queries from parity buffer -> fp16 QB, pos (fp32), zero SEXP
__global__ void k_gather(const int* __restrict__ p1, const int* __restrict__ p2, int buf) {
    __shared__ float sbuf[8];
    __shared__ float rowv[DIM];
    int k = blockIdx.x, d = threadIdx.x;
    int i1 = p1[k], i2 = p2[k];
    const float* XN = g_XN[buf];
    float a = XN[(size_t)i1 * DIM + d];
    float b = XN[(size_t)i2 * DIM + d];
    rowv[d] = a;
    float s = blockReduceSum256(a * b, sbuf);
    if (d == 0) { g_POS[k] = s * 10.f; g_SEXP[k] = 0.f; }
    __syncthreads();
    if (d < 128)
        ((uint*)g_QB4)[(size_t)k * 128 + d] = pack_f16(rowv[2*d], rowv[2*d + 1]);
}

// ---------------- fused LSE + QUANT kernel ----------------
// blocks [0, 8192): f16 MMA LSE GEMM tile (reads parity buf q&1)
// blocks [8192, 9216): quantize 32 rows + produce stage q+1 normals (buf (q+1)&1)

__device__ __forceinline__ void lse_body(char* dyn, int bx, int buf) {
    uint sbase = smem_u32(dyn);
    int tid  = threadIdx.x;
    int wid  = tid >> 5, lane = tid & 31;
    int wm   = wid >> 2, wn   = wid & 3;
    int bn   = bx & 255, bm = bx >> 8;

    const char* gA = (const char*)g_QB4       + (size_t)(bm * 128) * 512;
    const char* gB = (const char*)g_XNB4[buf] + (size_t)(bn * 128) * 512;

    uint acc[4][4][2];
    #pragma unroll
    for (int mt = 0; mt < 4; mt++)
        #pragma unroll
        for (int nt = 0; nt < 4; nt++) { acc[mt][nt][0] = 0u; acc[mt][nt][1] = 0u; }

    auto load_chunk = [&](int kc, int b) {
        uint abuf = sbase + (uint)b * 32768u;
        uint bbuf = abuf + 16384u;
        #pragma unroll
        for (int t = 0; t < 4; t++) {
            int i = tid + t * 256;
            int row = i >> 3, c = i & 7;
            uint soff = (uint)((row * 8 + (c ^ (row & 7))) * 16);
            cp16(abuf + soff, gA + (size_t)row * 512 + kc * 128 + c * 16);
            cp16(bbuf + soff, gB + (size_t)row * 512 + kc * 128 + c * 16);
        }
    };

    auto ldfrag = [&](uint abuf, uint bbuf, int ks, uint afr[4][4], uint bfr[4][2]) {
        #pragma unroll
        for (int mt = 0; mt < 4; mt++) {
            int row = wm * 64 + mt * 16 + (lane & 15);
            int chunk = ks * 2 + (lane >> 4);
            uint addr = abuf + (uint)((row * 8 + (chunk ^ (row & 7))) * 16);
            ldm4(afr[mt][0], afr[mt][1], afr[mt][2], afr[mt][3], addr);
        }
        #pragma unroll
        for (int p = 0; p < 2; p++) {
            int g = lane >> 3;
            int ntl = 2 * p + (g >> 1);
            int row = wn * 32 + ntl * 8 + (lane & 7);
            int chunk = ks * 2 + (g & 1);
            uint addr = bbuf + (uint)((row * 8 + (chunk ^ (row & 7))) * 16);
            ldm4(bfr[2*p][0], bfr[2*p][1], bfr[2*p+1][0], bfr[2*p+1][1], addr);
        }
    };

    load_chunk(0, 0);
    asm volatile("cp.async.commit_group;" ::: "memory");
    load_chunk(1, 1);
    asm volatile("cp.async.commit_group;" ::: "memory");

    #pragma unroll
    for (int kc = 0; kc < 4; kc++) {
        if (kc < 3) asm volatile("cp.async.wait_group 1;" ::: "memory");
        else        asm volatile("cp.async.wait_group 0;" ::: "memory");
        __syncthreads();

        uint abuf = sbase + (uint)(kc & 1) * 32768u;
        uint bbuf = abuf + 16384u;

        uint afr[2][4][4];
        uint bfr[2][4][2];
        ldfrag(abuf, bbuf, 0, afr[0], bfr[0]);

        #pragma unroll
        for (int ks = 0; ks < 4; ks++) {
            int cur = ks & 1;
            if (ks < 3) ldfrag(abuf, bbuf, ks + 1, afr[cur ^ 1], bfr[cur ^ 1]);
            #pragma unroll
            for (int mt = 0; mt < 4; mt++)
                #pragma unroll
                for (int nt = 0; nt < 4; nt++)
                    mma_f16acc(acc[mt][nt], afr[cur][mt], bfr[cur][nt]);
        }
        __syncthreads();
        if (kc < 2) {
            load_chunk(kc + 2, kc & 1);
            asm volatile("cp.async.commit_group;" ::: "memory");
        }
    }

    float* red = (float*)dyn;   // 128 rows x 4 n-warps
    float s0[4], s1[4];
    #pragma unroll
    for (int mt = 0; mt < 4; mt++) {
        float a0 = 0.f, a1 = 0.f;
        #pragma unroll
        for (int nt = 0; nt < 4; nt++) {
            float2 f0 = __half22float2(*(const __half2*)&acc[mt][nt][0]);
            float2 f1 = __half22float2(*(const __half2*)&acc[mt][nt][1]);
            a0 += __expf(10.f * f0.x) + __expf(10.f * f0.y);
            a1 += __expf(10.f * f1.x) + __expf(10.f * f1.y);
        }
        #pragma unroll
        for (int o = 1; o < 4; o <<= 1) {
            a0 += __shfl_xor_sync(0xffffffffu, a0, o);
            a1 += __shfl_xor_sync(0xffffffffu, a1, o);
        }
        s0[mt] = a0; s1[mt] = a1;
    }
    __syncthreads();
    if ((lane & 3) == 0) {
        int rbase = wm * 64 + (lane >> 2);
        #pragma unroll
        for (int mt = 0; mt < 4; mt++) {
            red[(rbase + mt * 16)     * 4 + wn] = s0[mt];
            red[(rbase + mt * 16 + 8) * 4 + wn] = s1[mt];
        }
    }
    __syncthreads();
    int tid2 = threadIdx.x;
    if (tid2 < 128) {
        float s = red[tid2 * 4] + red[tid2 * 4 + 1] + red[tid2 * 4 + 2] + red[tid2 * 4 + 3];
        atomicAdd(&g_SEXP[bm * 128 + tid2], s);
    }
}

__device__ __forceinline__ void quant_body(char* dyn, int qb,
                                           const float* __restrict__ CB,
                                           float* __restrict__ out,
                                           int q, int first, int last) {
    float (*rs)[DIM] = (float(*)[DIM])dyn;      // 32KB from dynamic smem
    __shared__ ull   wmin[32][8];
    __shared__ float rowsum[32][8];
    __shared__ int   idxs[32];
    __shared__ float rr_s[32];
    __shared__ float inv_s[32];

    int tid = threadIdx.x;
    int lane = tid & 31, w = tid >> 5;
    int i0 = qb * 32;
    int nbuf = (q + 1) & 1;

    #pragma unroll
    for (int i = 0; i < 8; i++) {
        int lin = tid + i * 256;
        int m = lin >> 6, c = lin & 63;
        ((float4*)&rs[m][0])[c] = *(const float4*)(g_RES + (size_t)(i0 + m) * DIM + c * 4);
    }
    if (tid < 32) rr_s[tid] = g_RR[i0 + tid];
    __syncthreads();

    int j = tid;
    uint rs_base = smem_u32(&rs[0][0]);
    ull dot2[32];
    #pragma unroll
    for (int m = 0; m < 32; m++) dot2[m] = 0ull;

    const float2* ctp = g_CTP + (size_t)q * 128 * NE;
    #pragma unroll 2
    for (int dpc = 0; dpc < 32; dpc++) {
        ull ct[4];
        #pragma unroll
        for (int c = 0; c < 4; c++)
            ct[c] = *(const ull*)&ctp[(dpc * 4 + c) * NE + j];
        #pragma unroll
        for (int m = 0; m < 32; m++) {
            uint addr = rs_base + (uint)(m * 1024 + dpc * 32);
            ull r0, r1, r2, r3;
            lds2x64(r0, r1, addr);
            lds2x64(r2, r3, addr + 16u);
            fma2(dot2[m], r0, ct[0]);
            fma2(dot2[m], r1, ct[1]);
            fma2(dot2[m], r2, ct[2]);
            fma2(dot2[m], r3, ct[3]);
        }
    }

    float ce = g_CE[q * NE + j];
    #pragma unroll
    for (int m = 0; m < 32; m++) {
        float2 f = u2f(dot2[m]);
        float dotv = f.x + f.y;
        float t1 = fmaf(-2.f, dotv, rr_s[m]);
        float d2 = t1 + ce;
        unsigned u = __float_as_uint(d2);
        u = (u & 0x80000000u) ? ~u : (u | 0x80000000u);
        ull key = ((ull)u << 32) | (ull)(unsigned)j;
        #pragma unroll
        for (int o = 16; o; o >>= 1) {
            ull other = __shfl_down_sync(0xffffffffu, key, o);
            if (other < key) key = other;
        }
        if (lane == 0) wmin[m][w] = key;
    }
    __syncthreads();

    if (tid < 32) {
        ull best = wmin[tid][0];
        #pragma unroll
        for (int t = 1; t < 8; t++) if (wmin[tid][t] < best) best = wmin[tid][t];
        int id = (int)(best & 0xffu);
        idxs[tid] = id;
        out[OFF_IDX + (size_t)(i0 + tid) * NQ + q] = (float)id;
    }
    __syncthreads();

    const float* cb = CB + (size_t)q * NE * DIM;
    #pragma unroll 4
    for (int m = 0; m < 32; m++) {
        float cv = cb[(size_t)idxs[m] * DIM + tid];
        float nr = rs[m][tid] - cv;
        size_t go = (size_t)(i0 + m) * DIM + tid;
        g_RES[go] = nr;
        out[go] = first ? cv : (out[go] + cv);
        rs[m][tid] = nr;
        float v = nr * nr;
        #pragma unroll
        for (int o = 16; o; o >>= 1) v += __shfl_down_sync(0xffffffffu, v, o);
        if (lane == 0) rowsum[m][w] = v;
    }
    __syncthreads();

    if (tid < 32) {
        float rr = 0.f;
        #pragma unroll
        for (int t = 0; t < 8; t++) rr += rowsum[tid][t];
        rr_s[tid] = rr;
        inv_s[tid] = rsqrtf(rr + 1e-12f);
        if (!last) g_RR[i0 + tid] = rr;
    }
    __syncthreads();

    if (tid == 0) {
        float s = 0.f;
        #pragma unroll
        for (int m = 0; m < 32; m++) s += rr_s[m];
        atomicAdd(&g_VQ[q], s);
    }

    if (!last) {
        float* XNn = g_XN[nbuf];
        #pragma unroll
        for (int i = 0; i < 8; i++) {
            int lin = tid + i * 256;
            int m = lin >> 6, c = lin & 63;
            float inv = inv_s[m];
            float4 v = ((const float4*)&rs[m][0])[c];
            v.x *= inv; v.y *= inv; v.z *= inv; v.w *= inv;
            *(float4*)(XNn + (size_t)(i0 + m) * DIM + c * 4) = v;
        }
        #pragma unroll
        for (int i = 0; i < 4; i++) {
            int lin = tid + i * 256;
            int m = lin >> 5, c = lin & 31;
            float inv = inv_s[m];
            const float* r = &rs[m][c * 8];
            uint4 p;
            p.x = pack_f16(r[0]*inv, r[1]*inv);
            p.y = pack_f16(r[2]*inv, r[3]*inv);
            p.z = pack_f16(r[4]*inv, r[5]*inv);
            p.w = pack_f16(r[6]*inv, r[7]*inv);
            g_XNB4[nbuf][(size_t)(i0 + m) * 32 + c] = p;
        }
    }
}

__global__ void __launch_bounds__(256, 2) k_fused(const float* __restrict__ CB,
                                                  float* __restrict__ out,
                                                  int q, int first, int last) {
    extern __shared__ char dyn[];
    int bx = blockIdx.x;
    if (bx < LSE_BLOCKS) lse_body(dyn, bx, q & 1);
    else                 quant_body(dyn, bx - LSE_BLOCKS, CB, out, q, first, last);
}

__global__ void k_outer(float* __restrict__ out, int q) {
    __shared__ float sbuf[8];
    float acc = 0.f;
    for (int k = threadIdx.x; k < KP; k += 256)
        acc += logf(g_SEXP[k]) - g_POS[k];
    float s = blockReduceSum256(acc, sbuf);
    if (threadIdx.x == 0) out[OFF_OUTER + q] = s / (float)KP;
}

__global__ void k_vqmean(float* __restrict__ out) {
    if (threadIdx.x == 0) {
        float s = g_VQ[0] + g_VQ[1] + g_VQ[2] + g_VQ[3];
        out[OFF_MEAN] = s * (1.25f / (4.f * (float)NROWS * (float)DIM));
    }
}

// ---------------- launch ----------------
extern "C" void kernel_launch(void* const* d_in, const int* in_sizes, int n_in,
                              void* d_out, int out_size) {
    const float* x  = (const float*)d_in[0];
    const float* cb = (const float*)d_in[1];
    const int*   p1 = (const int*)d_in[2];
    const int*   p2 = (const int*)d_in[3];
    float* out = (float*)d_out;

    cudaFuncSetAttribute(k_fused, cudaFuncAttributeMaxDynamicSharedMemorySize, 65536);

    k_init<<<NROWS * DIM / 4 / 256, 256>>>(x);
    k_prep<<<dim3(NE, NQ), 256>>>(cb);
    k_norm<<<NROWS, 256>>>();
    for (int q = 0; q < NQ; q++) {
        k_gather<<<KP, 256>>>(p1, p2, q & 1);
        k_fused<<<LSE_BLOCKS + QUANT_BLOCKS, 256, 65536>>>(cb, out, q, q == 0, q == NQ - 1);
        k_outer<<<1, 256>>>(out, q);
    }
    k_vqmean<<<1, 32>>>(out);
}